// round 4
// baseline (speedup 1.0000x reference)
#include <cuda_runtime.h>
#include <cstdint>

#define NBLK   128
#define NTHR   128
#define SEQ    1024
#define TLEN   256
#define HID    512
#define NSTEPS (SEQ + TLEN)
#define BTILE  64      // batches per CTA
#define HTILE  16      // hidden units per CTA (=> 64 gate cols)
#define NC     64      // gate columns per CTA
#define WS     516     // W_s row stride (512 + 4 pad)
#define AS     132     // A_s row stride (128 + 4 pad)
#define GS     68      // gates_s row stride (64 + 4 pad)
#define CHUNK  128     // K chunk
#define CHUNK_F (BTILE * AS)

__device__ unsigned g_bar_count;
__device__ unsigned g_bar_gen;
__device__ float    g_h[2][256][HID];   // ping-pong hidden state

__device__ __forceinline__ float tf32r(float x) {
    unsigned t;
    asm("cvt.rna.tf32.f32 %0, %1;" : "=r"(t) : "f"(x));
    return __uint_as_float(t);
}
__device__ __forceinline__ float sigm(float x) {
    return __fdividef(1.0f, 1.0f + __expf(-x));
}
__device__ __forceinline__ float tanh_f(float x) {
    return __fdividef(2.0f, 1.0f + __expf(-2.0f * x)) - 1.0f;
}

// Device-wide sense-free barrier (generation counter). 128 CTAs, 1/SM => co-resident.
__device__ __forceinline__ void gridbar() {
    __syncthreads();
    if (threadIdx.x == 0) {
        volatile unsigned* genp = &g_bar_gen;
        unsigned target = *genp;
        __threadfence();                       // release: h stores / atomics visible
        unsigned arr = atomicAdd(&g_bar_count, 1u);
        if (arr == NBLK - 1) {
            g_bar_count = 0u;
            __threadfence();
            atomicAdd(&g_bar_gen, 1u);
        } else {
            while (*genp == target) __nanosleep(32);
        }
        __threadfence();                       // acquire
    }
    __syncthreads();
}

__device__ __forceinline__ void load_w(const float* __restrict__ Whh,
                                       const float* __restrict__ bih,
                                       const float* __restrict__ bhh,
                                       const float* __restrict__ Wih,
                                       float* W_s, float* bias_s, float* wih_s,
                                       int h_base, int tid) {
    // SMEM gate-col n = g*16 + jj  <->  global gate row g*512 + h_base + jj
    for (int idx = tid; idx < NC * HID; idx += NTHR) {
        int n = idx >> 9;
        int k = idx & (HID - 1);
        int grow = (n >> 4) * HID + h_base + (n & 15);
        W_s[n * WS + k] = tf32r(Whh[grow * HID + k]);
    }
    if (tid < NC) {
        int grow = (tid >> 4) * HID + h_base + (tid & 15);
        bias_s[tid] = bih[grow] + bhh[grow];
        wih_s[tid]  = Wih[grow];
    }
}

__device__ __forceinline__ void copy_chunk(const float* __restrict__ hsrc,
                                           float* As, int kbase, int b_base, int tid) {
    unsigned sbase = (unsigned)__cvta_generic_to_shared(As);
    #pragma unroll
    for (int it = 0; it < 16; ++it) {
        int idx = it * NTHR + tid;          // 0..2047 (64 rows x 32 x 16B)
        int row = idx >> 5;
        int c4  = (idx & 31) * 4;
        const float* g = hsrc + (b_base + row) * HID + kbase + c4;
        unsigned s = sbase + (unsigned)(row * AS + c4) * 4u;
        asm volatile("cp.async.cg.shared.global [%0], [%1], 16;" :: "r"(s), "l"(g));
    }
}

#define MMA_TF32(C, A, B)                                                   \
    asm volatile(                                                           \
        "mma.sync.aligned.m16n8k8.row.col.f32.tf32.tf32.f32 "               \
        "{%0,%1,%2,%3}, {%4,%5,%6,%7}, {%8,%9}, {%0,%1,%2,%3};"             \
        : "+f"(C[0]), "+f"(C[1]), "+f"(C[2]), "+f"(C[3])                    \
        : "r"(A[0]), "r"(A[1]), "r"(A[2]), "r"(A[3]), "r"(B[0]), "r"(B[1]))

__global__ void __launch_bounds__(NTHR, 1)
lstm_seq2seq_kernel(const float* __restrict__ inputs,
                    const float* __restrict__ eWih, const float* __restrict__ eWhh,
                    const float* __restrict__ ebih, const float* __restrict__ ebhh,
                    const float* __restrict__ dWih, const float* __restrict__ dWhh,
                    const float* __restrict__ dbih, const float* __restrict__ dbhh,
                    const float* __restrict__ linW, const float* __restrict__ linb,
                    float* __restrict__ out) {
    extern __shared__ float sm[];
    float* W_s    = sm;                    // 64 x 516
    float* A_s    = W_s + NC * WS;         // 2 x 64 x 132 (double buffer)
    float* G_s    = A_s + 2 * CHUNK_F;     // 64 x 68
    float* bias_s = G_s + BTILE * GS;      // 64
    float* wih_s  = bias_s + NC;           // 64
    float* x_s    = wih_s + NC;            // 64

    const int tid    = threadIdx.x;
    const int bx     = blockIdx.x;
    const int b_base = (bx & 3) * BTILE;   // 4 batch tiles
    const int htile  = bx >> 2;            // 32 hidden tiles
    const int h_base = htile * HTILE;
    const int lane   = tid & 31;
    const int warp   = tid >> 5;
    const int wm     = warp >> 1;          // warp grid 2x2, warp tile 32x32
    const int wn     = warp & 1;
    const int jj     = tid & 15;
    const int bq     = tid >> 4;

    // Init: zero g_h[0] and d_out (poisoned by harness)
    {
        float* h0 = &g_h[0][0][0];
        for (int i = tid; i < 1024; i += NTHR) h0[bx * 1024 + i] = 0.0f;
        for (int i = tid; i < 512;  i += NTHR) out[bx * 512 + i] = 0.0f;
    }
    load_w(eWhh, ebih, ebhh, eWih, W_s, bias_s, wih_s, h_base, tid);

    const float lw  = linW[h_base + jj];
    const float lb0 = linb[0];
    float creg[8];                         // cell state lives in registers
    #pragma unroll
    for (int i = 0; i < 8; ++i) creg[i] = 0.0f;

    gridbar();

    for (int s = 0; s < NSTEPS; ++s) {
        const int  cur = s & 1;
        const int  nxt = cur ^ 1;
        const bool dec = (s >= SEQ);

        if (s == SEQ)  // switch to decoder weights (sync'd by first mainloop barrier)
            load_w(dWhh, dbih, dbhh, dWih, W_s, bias_s, wih_s, h_base, tid);

        if (tid < BTILE) {
            float xv;
            if (!dec)          xv = inputs[(b_base + tid) * SEQ + s];
            else if (s == SEQ) xv = inputs[(b_base + tid) * SEQ + (SEQ - 1)];
            else               xv = __ldcg(&out[(b_base + tid) * TLEN + (s - SEQ - 1)]);
            x_s[tid] = xv;
        }

        float C[2][4][4];
        #pragma unroll
        for (int t = 0; t < 2; ++t)
            #pragma unroll
            for (int u = 0; u < 4; ++u)
                #pragma unroll
                for (int r = 0; r < 4; ++r) C[t][u][r] = 0.0f;

        const float* hsrc = &g_h[cur][0][0];
        copy_chunk(hsrc, A_s, 0, b_base, tid);
        asm volatile("cp.async.commit_group;");

        #pragma unroll 1
        for (int ch = 0; ch < 4; ++ch) {
            if (ch < 3) {
                copy_chunk(hsrc, A_s + ((ch + 1) & 1) * CHUNK_F, (ch + 1) * CHUNK, b_base, tid);
                asm volatile("cp.async.commit_group;");
                asm volatile("cp.async.wait_group 1;");
            } else {
                asm volatile("cp.async.wait_group 0;");
            }
            __syncthreads();
            const float* Ab = A_s + (ch & 1) * CHUNK_F;
            const int    kb = ch * CHUNK;
            #pragma unroll
            for (int kk = 0; kk < CHUNK; kk += 8) {
                unsigned a[2][4], b[4][2];
                const int ar = wm * 32 + (lane >> 2);
                const int ac = kk + (lane & 3);
                #pragma unroll
                for (int t = 0; t < 2; ++t) {
                    const float* ap = Ab + (ar + t * 16) * AS + ac;
                    a[t][0] = __float_as_uint(ap[0]);
                    a[t][1] = __float_as_uint(ap[8 * AS]);
                    a[t][2] = __float_as_uint(ap[4]);
                    a[t][3] = __float_as_uint(ap[8 * AS + 4]);
                }
                const int bc = kb + kk + (lane & 3);
                #pragma unroll
                for (int u = 0; u < 4; ++u) {
                    const float* bp = W_s + (wn * 32 + u * 8 + (lane >> 2)) * WS + bc;
                    b[u][0] = __float_as_uint(bp[0]);
                    b[u][1] = __float_as_uint(bp[4]);
                }
                #pragma unroll
                for (int t = 0; t < 2; ++t)
                    #pragma unroll
                    for (int u = 0; u < 4; ++u)
                        MMA_TF32(C[t][u], a[t], b[u]);
            }
            __syncthreads();
        }

        // C frags -> gates SMEM
        #pragma unroll
        for (int t = 0; t < 2; ++t) {
            const int r = wm * 32 + t * 16 + (lane >> 2);
            #pragma unroll
            for (int u = 0; u < 4; ++u) {
                const int cc = wn * 32 + u * 8 + (lane & 3) * 2;
                *(float2*)&G_s[r * GS + cc]       = make_float2(C[t][u][0], C[t][u][1]);
                *(float2*)&G_s[(r + 8) * GS + cc] = make_float2(C[t][u][2], C[t][u][3]);
            }
        }
        __syncthreads();

        // Epilogue: 8 cells per thread; cell (b, jj), c in registers
        #pragma unroll
        for (int ci = 0; ci < 8; ++ci) {
            const int   b  = bq + ci * 8;
            const float xv = x_s[b];
            const float* gr = G_s + b * GS;
            const float gi = gr[jj]      + bias_s[jj]      + xv * wih_s[jj];
            const float gf = gr[16 + jj] + bias_s[16 + jj] + xv * wih_s[16 + jj];
            const float gg = gr[32 + jj] + bias_s[32 + jj] + xv * wih_s[32 + jj];
            const float go = gr[48 + jj] + bias_s[48 + jj] + xv * wih_s[48 + jj];
            const float cn = sigm(gf) * creg[ci] + sigm(gi) * tanh_f(gg);
            creg[ci] = cn;
            float h = sigm(go) * tanh_f(cn);
            h = tf32r(h);                              // producer-side tf32 rounding
            g_h[nxt][b_base + b][h_base + jj] = h;
            if (dec) {
                float p = h * lw;
                #pragma unroll
                for (int off = 8; off; off >>= 1)
                    p += __shfl_xor_sync(0xffffffffu, p, off);
                if (jj == 0) {
                    if (htile == 0) p += lb0;
                    atomicAdd(&out[(b_base + b) * TLEN + (s - SEQ)], p);
                }
            }
        }
        gridbar();
    }
}

extern "C" void kernel_launch(void* const* d_in, const int* in_sizes, int n_in,
                              void* d_out, int out_size) {
    const float* inputs = (const float*)d_in[0];
    const float* eWih   = (const float*)d_in[1];
    const float* eWhh   = (const float*)d_in[2];
    const float* ebih   = (const float*)d_in[3];
    const float* ebhh   = (const float*)d_in[4];
    const float* dWih   = (const float*)d_in[5];
    const float* dWhh   = (const float*)d_in[6];
    const float* dbih   = (const float*)d_in[7];
    const float* dbhh   = (const float*)d_in[8];
    const float* linW   = (const float*)d_in[9];
    const float* linb   = (const float*)d_in[10];
    float* out = (float*)d_out;

    const int smem = (NC * WS + 2 * CHUNK_F + BTILE * GS + 3 * NC) * sizeof(float); // 217856 B
    cudaFuncSetAttribute(lstm_seq2seq_kernel,
                         cudaFuncAttributeMaxDynamicSharedMemorySize, smem);
    lstm_seq2seq_kernel<<<NBLK, NTHR, smem>>>(inputs, eWih, eWhh, ebih, ebhh,
                                              dWih, dWhh, dbih, dbhh, linW, linb, out);
}